// round 1
// baseline (speedup 1.0000x reference)
#include <cuda_runtime.h>

// ---------------- problem constants ----------------
#define CB   4
#define CS   2048
#define CT   256
#define CH   2048
#define CNH  16
#define CHD  128

// ---------------- scratch (static __device__, per harness rules) ----------------
__device__ float g_Q [(size_t)CB * CS * CH];           // (b,s,h)
__device__ float g_K [(size_t)CB * CT * CH];           // (b,t,h)
__device__ float g_V [(size_t)CB * CT * CH];           // (b,t,h)
__device__ float g_Vt[(size_t)CB * CNH * CHD * CT];    // (b,h,d,t)
__device__ float g_Sc[(size_t)CB * CNH * CS * CT];     // (b,h,s,t)
__device__ float g_Cx[(size_t)CB * CS * CH];           // ctx (b,s,h)

// ---------------- helpers ----------------
__device__ __forceinline__ unsigned f2tf(float x) {
    unsigned r;
    asm("cvt.rna.tf32.f32 %0, %1;" : "=r"(r) : "f"(x));
    return r;
}

__device__ __forceinline__ void mma8(float* c, const unsigned* a, const unsigned* b) {
    asm volatile(
        "mma.sync.aligned.m16n8k8.row.col.f32.tf32.tf32.f32 "
        "{%0,%1,%2,%3},{%4,%5,%6,%7},{%8,%9},{%0,%1,%2,%3};\n"
        : "+f"(c[0]), "+f"(c[1]), "+f"(c[2]), "+f"(c[3])
        : "r"(a[0]), "r"(a[1]), "r"(a[2]), "r"(a[3]), "r"(b[0]), "r"(b[1]));
}

// ---------------- generic batched NT tf32 GEMM ----------------
// C[M,N] = A[M,K] * B[N,K]^T  (+ bias / epilogue per mode)
// mode 0: plain (+bias if non-null)
// mode 1: scores epilogue: *1/sqrt(128), clip +-50, mask==0 -> -50
// mode 2: (+bias) * clamp(rs, 0, 0.3)
#define BM  128
#define BN  128
#define BKK 32
#define PAD 36   // floats per smem row (conflict-free, float4-aligned)

__global__ void gemm_tf32_nt(
    const float* __restrict__ A, const float* __restrict__ Bm,
    const float* __restrict__ bias, float* __restrict__ C,
    int M, int N, int K, int lda, int ldb, int ldc,
    long long aSb, long long aSh, long long bSb, long long bSh,
    long long cSb, long long cSh,
    int mode, const int* __restrict__ mask, const float* __restrict__ rsPtr)
{
    extern __shared__ unsigned sm[];
    unsigned* sA = sm;                    // 2 * BM * PAD
    unsigned* sB = sm + 2 * BM * PAD;     // 2 * BN * PAD

    const int z  = blockIdx.z;
    const int bb = z >> 4;
    const int hh = z & 15;
    A  += (size_t)(bb * aSb + hh * aSh);
    Bm += (size_t)(bb * bSb + hh * bSh);
    C  += (size_t)(bb * cSb + hh * cSh);

    const int tid  = threadIdx.x;
    const int warp = tid >> 5, lane = tid & 31;
    const int wm   = warp >> 1, wn = warp & 1;
    const int g    = lane >> 2, tg = lane & 3;

    const int rowA0 = blockIdx.y * BM;
    const int rowB0 = blockIdx.x * BN;

    // per-thread gmem->smem mapping: 4 float4 each for A and B tiles
    int lr[4], lc[4];
#pragma unroll
    for (int i = 0; i < 4; i++) {
        int li = tid + i * 256;
        lr[i] = li >> 3;
        lc[i] = (li & 7) * 4;
    }

    float4 ra[4], rb[4];
    float acc[2][8][4];
#pragma unroll
    for (int mi = 0; mi < 2; mi++)
#pragma unroll
        for (int ni = 0; ni < 8; ni++)
#pragma unroll
            for (int q = 0; q < 4; q++) acc[mi][ni][q] = 0.f;

    const int nkt = K / BKK;

    // prologue: load k-tile 0 and stage to smem buffer 0
#pragma unroll
    for (int i = 0; i < 4; i++) {
        ra[i] = *(const float4*)(A  + (size_t)(rowA0 + lr[i]) * lda + lc[i]);
        rb[i] = *(const float4*)(Bm + (size_t)(rowB0 + lr[i]) * ldb + lc[i]);
    }
#pragma unroll
    for (int i = 0; i < 4; i++) {
        unsigned* pa = sA + lr[i] * PAD + lc[i];
        pa[0] = f2tf(ra[i].x); pa[1] = f2tf(ra[i].y); pa[2] = f2tf(ra[i].z); pa[3] = f2tf(ra[i].w);
        unsigned* pb = sB + lr[i] * PAD + lc[i];
        pb[0] = f2tf(rb[i].x); pb[1] = f2tf(rb[i].y); pb[2] = f2tf(rb[i].z); pb[3] = f2tf(rb[i].w);
    }
    __syncthreads();

    for (int kt = 0; kt < nkt; kt++) {
        const int cur = kt & 1;
        if (kt + 1 < nkt) {
            const int ko = (kt + 1) * BKK;
#pragma unroll
            for (int i = 0; i < 4; i++) {
                ra[i] = *(const float4*)(A  + (size_t)(rowA0 + lr[i]) * lda + ko + lc[i]);
                rb[i] = *(const float4*)(Bm + (size_t)(rowB0 + lr[i]) * ldb + ko + lc[i]);
            }
        }
        const unsigned* cA = sA + cur * BM * PAD;
        const unsigned* cB = sB + cur * BN * PAD;
#pragma unroll
        for (int ks = 0; ks < 4; ks++) {
            const int ko = ks * 8;
            unsigned af[2][4];
#pragma unroll
            for (int mi = 0; mi < 2; mi++) {
                const unsigned* p = cA + (wm * 32 + mi * 16 + g) * PAD + ko;
                af[mi][0] = p[tg];
                af[mi][1] = p[8 * PAD + tg];
                af[mi][2] = p[tg + 4];
                af[mi][3] = p[8 * PAD + tg + 4];
            }
            unsigned bf[8][2];
#pragma unroll
            for (int ni = 0; ni < 8; ni++) {
                const unsigned* p = cB + (wn * 64 + ni * 8 + g) * PAD + ko;
                bf[ni][0] = p[tg];
                bf[ni][1] = p[tg + 4];
            }
#pragma unroll
            for (int mi = 0; mi < 2; mi++)
#pragma unroll
                for (int ni = 0; ni < 8; ni++)
                    mma8(acc[mi][ni], af[mi], bf[ni]);
        }
        if (kt + 1 < nkt) {
            const int nb = cur ^ 1;
            unsigned* dA = sA + nb * BM * PAD;
            unsigned* dB = sB + nb * BN * PAD;
#pragma unroll
            for (int i = 0; i < 4; i++) {
                unsigned* pa = dA + lr[i] * PAD + lc[i];
                pa[0] = f2tf(ra[i].x); pa[1] = f2tf(ra[i].y); pa[2] = f2tf(ra[i].z); pa[3] = f2tf(ra[i].w);
                unsigned* pb = dB + lr[i] * PAD + lc[i];
                pb[0] = f2tf(rb[i].x); pb[1] = f2tf(rb[i].y); pb[2] = f2tf(rb[i].z); pb[3] = f2tf(rb[i].w);
            }
            __syncthreads();
        }
    }

    // epilogue
    float rs = 1.0f;
    if (mode == 2) {
        float r0 = *rsPtr;
        rs = fminf(fmaxf(r0, 0.f), 0.3f);
    }
    const float INV_SC = 0.08838834764831845f;  // 1/sqrt(128)
#pragma unroll
    for (int mi = 0; mi < 2; mi++) {
#pragma unroll
        for (int half = 0; half < 2; half++) {
            const int row = rowA0 + wm * 32 + mi * 16 + g + half * 8;
#pragma unroll
            for (int ni = 0; ni < 8; ni++) {
                const int col = rowB0 + wn * 64 + ni * 8 + 2 * tg;
                float v0 = acc[mi][ni][half * 2 + 0];
                float v1 = acc[mi][ni][half * 2 + 1];
                if (mode == 1) {
                    v0 *= INV_SC; v1 *= INV_SC;
                    v0 = fminf(fmaxf(v0, -50.f), 50.f);
                    v1 = fminf(fmaxf(v1, -50.f), 50.f);
                    if (mask[bb * CT + col]     == 0) v0 = -50.f;
                    if (mask[bb * CT + col + 1] == 0) v1 = -50.f;
                } else {
                    if (bias) { v0 += bias[col]; v1 += bias[col + 1]; }
                    v0 *= rs; v1 *= rs;
                }
                *(float2*)(C + (size_t)row * ldc + col) = make_float2(v0, v1);
            }
        }
    }
}

// ---------------- V transpose: (b,t,h0,d) -> (b,h0,d,t) ----------------
__global__ void transpose_v(const float* __restrict__ V, float* __restrict__ Vt) {
    __shared__ float tile[32][33];
    const int z  = blockIdx.z;
    const int bb = z >> 4, hh = z & 15;
    const float* src = V + (size_t)bb * CT * CH + hh * CHD;   // [t][d], row stride CH
    float*       dst = Vt + (size_t)z * CHD * CT;             // [d][t], row stride CT
    const int t0 = blockIdx.x * 32, d0 = blockIdx.y * 32;
#pragma unroll
    for (int i = 0; i < 4; i++) {
        int t = t0 + threadIdx.y + i * 8;
        tile[threadIdx.y + i * 8][threadIdx.x] = src[(size_t)t * CH + d0 + threadIdx.x];
    }
    __syncthreads();
#pragma unroll
    for (int i = 0; i < 4; i++) {
        int d = d0 + threadIdx.y + i * 8;
        dst[(size_t)d * CT + t0 + threadIdx.x] = tile[threadIdx.x][threadIdx.y + i * 8];
    }
}

// ---------------- softmax over rows of 256 (warp per row) ----------------
__global__ void softmax_kernel(float* __restrict__ Sc) {
    const int warp = threadIdx.x >> 5, lane = threadIdx.x & 31;
    const size_t row = (size_t)blockIdx.x * 8 + warp;
    float4* p = (float4*)(Sc + row * CT);
    float4 a = p[lane];
    float4 b = p[lane + 32];
    float m = fmaxf(fmaxf(fmaxf(a.x, a.y), fmaxf(a.z, a.w)),
                    fmaxf(fmaxf(b.x, b.y), fmaxf(b.z, b.w)));
#pragma unroll
    for (int o = 16; o; o >>= 1) m = fmaxf(m, __shfl_xor_sync(0xffffffffu, m, o));
    a.x = __expf(a.x - m); a.y = __expf(a.y - m); a.z = __expf(a.z - m); a.w = __expf(a.w - m);
    b.x = __expf(b.x - m); b.y = __expf(b.y - m); b.z = __expf(b.z - m); b.w = __expf(b.w - m);
    float s = a.x + a.y + a.z + a.w + b.x + b.y + b.z + b.w;
#pragma unroll
    for (int o = 16; o; o >>= 1) s += __shfl_xor_sync(0xffffffffu, s, o);
    const float inv = 1.f / s;
    a.x *= inv; a.y *= inv; a.z *= inv; a.w *= inv;
    b.x *= inv; b.y *= inv; b.z *= inv; b.w *= inv;
    p[lane] = a;
    p[lane + 32] = b;
}

// ---------------- LayerNorm in place over rows of 2048 ----------------
__global__ void ln_kernel(float* __restrict__ X,
                          const float* __restrict__ gamma,
                          const float* __restrict__ beta) {
    __shared__ float red[8];
    __shared__ float sstat[2];
    const int tid = threadIdx.x, lane = tid & 31, warp = tid >> 5;
    float* p = X + (size_t)blockIdx.x * CH;
    float4 v0 = ((const float4*)p)[tid];
    float4 v1 = ((const float4*)p)[tid + 256];

    float s = v0.x + v0.y + v0.z + v0.w + v1.x + v1.y + v1.z + v1.w;
#pragma unroll
    for (int o = 16; o; o >>= 1) s += __shfl_xor_sync(0xffffffffu, s, o);
    if (lane == 0) red[warp] = s;
    __syncthreads();
    if (tid == 0) {
        float t = 0.f;
#pragma unroll
        for (int i = 0; i < 8; i++) t += red[i];
        sstat[0] = t * (1.f / CH);
    }
    __syncthreads();
    const float mu = sstat[0];

    float q = 0.f;
    {
        float d;
        d = v0.x - mu; q += d * d; d = v0.y - mu; q += d * d;
        d = v0.z - mu; q += d * d; d = v0.w - mu; q += d * d;
        d = v1.x - mu; q += d * d; d = v1.y - mu; q += d * d;
        d = v1.z - mu; q += d * d; d = v1.w - mu; q += d * d;
    }
#pragma unroll
    for (int o = 16; o; o >>= 1) q += __shfl_xor_sync(0xffffffffu, q, o);
    __syncthreads();
    if (lane == 0) red[warp] = q;
    __syncthreads();
    if (tid == 0) {
        float t = 0.f;
#pragma unroll
        for (int i = 0; i < 8; i++) t += red[i];
        sstat[1] = rsqrtf(t * (1.f / CH) + 1e-5f);
    }
    __syncthreads();
    const float inv = sstat[1];

    float4 gm0 = ((const float4*)gamma)[tid];
    float4 gm1 = ((const float4*)gamma)[tid + 256];
    float4 bt0 = ((const float4*)beta)[tid];
    float4 bt1 = ((const float4*)beta)[tid + 256];
    v0.x = (v0.x - mu) * inv * gm0.x + bt0.x;
    v0.y = (v0.y - mu) * inv * gm0.y + bt0.y;
    v0.z = (v0.z - mu) * inv * gm0.z + bt0.z;
    v0.w = (v0.w - mu) * inv * gm0.w + bt0.w;
    v1.x = (v1.x - mu) * inv * gm1.x + bt1.x;
    v1.y = (v1.y - mu) * inv * gm1.y + bt1.y;
    v1.z = (v1.z - mu) * inv * gm1.z + bt1.z;
    v1.w = (v1.w - mu) * inv * gm1.w + bt1.w;
    ((float4*)p)[tid] = v0;
    ((float4*)p)[tid + 256] = v1;
}

// ---------------- host launch ----------------
extern "C" void kernel_launch(void* const* d_in, const int* in_sizes, int n_in,
                              void* d_out, int out_size) {
    const float* hs  = (const float*)d_in[0];
    const float* at  = (const float*)d_in[1];
    const int*   msk = (const int*)  d_in[2];
    const float* Wq  = (const float*)d_in[3];
    const float* bq  = (const float*)d_in[4];
    const float* Wk  = (const float*)d_in[5];
    const float* bk  = (const float*)d_in[6];
    const float* Wv  = (const float*)d_in[7];
    const float* bv  = (const float*)d_in[8];
    const float* Wo  = (const float*)d_in[9];
    const float* bo  = (const float*)d_in[10];
    const float* gm  = (const float*)d_in[11];
    const float* bt  = (const float*)d_in[12];
    const float* rs  = (const float*)d_in[13];
    float* out = (float*)d_out;

    float *Q, *Kb, *Vb, *Vt, *Sc, *Cx;
    cudaGetSymbolAddress((void**)&Q,  g_Q);
    cudaGetSymbolAddress((void**)&Kb, g_K);
    cudaGetSymbolAddress((void**)&Vb, g_V);
    cudaGetSymbolAddress((void**)&Vt, g_Vt);
    cudaGetSymbolAddress((void**)&Sc, g_Sc);
    cudaGetSymbolAddress((void**)&Cx, g_Cx);

    const size_t smemB = (size_t)2 * (BM + BN) * PAD * sizeof(unsigned);  // 73728
    cudaFuncSetAttribute(gemm_tf32_nt, cudaFuncAttributeMaxDynamicSharedMemorySize, (int)smemB);

    // Q projection: (B*S, H) = hs * Wq^T + bq
    gemm_tf32_nt<<<dim3(CH / BN, (CB * CS) / BM, 1), 256, smemB>>>(
        hs, Wq, bq, Q, CB * CS, CH, CH, CH, CH, CH,
        0, 0, 0, 0, 0, 0, 0, nullptr, nullptr);

    // K projection: (B*T, H) = at * Wk^T + bk
    gemm_tf32_nt<<<dim3(CH / BN, (CB * CT) / BM, 1), 256, smemB>>>(
        at, Wk, bk, Kb, CB * CT, CH, CH, CH, CH, CH,
        0, 0, 0, 0, 0, 0, 0, nullptr, nullptr);

    // V projection
    gemm_tf32_nt<<<dim3(CH / BN, (CB * CT) / BM, 1), 256, smemB>>>(
        at, Wv, bv, Vb, CB * CT, CH, CH, CH, CH, CH,
        0, 0, 0, 0, 0, 0, 0, nullptr, nullptr);

    // V transpose per head
    transpose_v<<<dim3(CT / 32, CHD / 32, CB * CNH), dim3(32, 8)>>>(Vb, Vt);

    // scores: per (b,h) S[s,t] = Q_bh * K_bh^T, scaled/clipped/masked
    gemm_tf32_nt<<<dim3(CT / BN, CS / BM, CB * CNH), 256, smemB>>>(
        Q, Kb, nullptr, Sc, CS, CT, CHD, CH, CH, CT,
        (long long)CS * CH, (long long)CHD,
        (long long)CT * CH, (long long)CHD,
        (long long)CNH * CS * CT, (long long)CS * CT,
        1, msk, nullptr);

    // softmax rows
    softmax_kernel<<<(CB * CNH * CS) / 8, 256>>>(Sc);

    // ctx: per (b,h) C[s,d] = P * V  -> written into (b,s,h) layout
    gemm_tf32_nt<<<dim3(CHD / BN, CS / BM, CB * CNH), 256, smemB>>>(
        Sc, Vt, nullptr, Cx, CS, CHD, CT, CT, CT, CH,
        (long long)CNH * CS * CT, (long long)CS * CT,
        (long long)CNH * CHD * CT, (long long)CHD * CT,
        (long long)CS * CH, (long long)CHD,
        0, nullptr, nullptr);

    // O projection with bias + residual scale -> d_out
    gemm_tf32_nt<<<dim3(CH / BN, (CB * CS) / BM, 1), 256, smemB>>>(
        Cx, Wo, bo, out, CB * CS, CH, CH, CH, CH, CH,
        0, 0, 0, 0, 0, 0, 2, nullptr, rs);

    // LayerNorm in place
    ln_kernel<<<CB * CS, 256>>>(out, gm, bt);
}

// round 4
// speedup vs baseline: 1.3705x; 1.3705x over previous
#include <cuda_runtime.h>
#include <cuda_fp16.h>
#include <cstdint>

// ---------------- problem constants ----------------
#define CB   4
#define CS   2048
#define CT   256
#define CH   2048
#define CNH  16
#define CHD  128

// ---------------- scratch ----------------
__device__ __align__(1024) __half g_Qh [(size_t)CB * CS * CH];         // (b,s,h)
__device__ __align__(1024) __half g_Kh [(size_t)CB * CT * CH];         // (b,t,h)
__device__ __align__(1024) __half g_Vh [(size_t)CB * CT * CH];         // (b,t,h)
__device__ __align__(1024) __half g_Vth[(size_t)CB * CNH * CHD * CT];  // (b,h,d,t)
__device__ __align__(1024) float  g_Sc [(size_t)CB * CNH * CS * CT];   // (b,h,s,t) f32
__device__ __align__(1024) __half g_Ph [(size_t)CB * CNH * CS * CT];   // probs half
__device__ __align__(1024) __half g_Cxh[(size_t)CB * CS * CH];         // ctx (b,s,h)

// ---------------- helpers ----------------
__device__ __forceinline__ uint32_t smem_u32(const void* p) {
    uint32_t a;
    asm("{ .reg .u64 t; cvta.to.shared.u64 t, %1; cvt.u32.u64 %0, t; }" : "=r"(a) : "l"(p));
    return a;
}
#define SWZ(o) ((o) ^ (((o) >> 3) & 0x70))

__device__ __forceinline__ void ldsm4(unsigned& r0, unsigned& r1, unsigned& r2, unsigned& r3,
                                      uint32_t addr) {
    asm volatile("ldmatrix.sync.aligned.m8n8.x4.shared.b16 {%0,%1,%2,%3}, [%4];"
                 : "=r"(r0), "=r"(r1), "=r"(r2), "=r"(r3) : "r"(addr));
}
__device__ __forceinline__ void mma16816(float* c, const unsigned* a, const unsigned* b) {
    asm volatile(
        "mma.sync.aligned.m16n8k16.row.col.f32.f16.f16.f32 "
        "{%0,%1,%2,%3},{%4,%5,%6,%7},{%8,%9},{%0,%1,%2,%3};\n"
        : "+f"(c[0]), "+f"(c[1]), "+f"(c[2]), "+f"(c[3])
        : "r"(a[0]), "r"(a[1]), "r"(a[2]), "r"(a[3]), "r"(b[0]), "r"(b[1]));
}
__device__ __forceinline__ unsigned pack2(float x, float y) {
    __half2 h = __floats2half2_rn(x, y);
    return *reinterpret_cast<unsigned*>(&h);
}

// ---------------- fp16 mma.sync batched NT GEMM ----------------
// C[M,N] = A[M,K] * B[N,K]^T. BM=BN=128, BK=32, 256 threads, warp tile 32x64.
// AH/BH: operand stored as half (else float, converted at staging).
// OH: output written as half.
// mode 0: (+bias)   mode 1: scores (scale, clip, mask)   mode 2: (+bias)*clamp(rs)
template<bool AH, bool BH, bool OH>
__global__ void __launch_bounds__(256, 2) hgemm(
    const void* __restrict__ Av, const void* __restrict__ Bv,
    const float* __restrict__ bias, void* __restrict__ Cv,
    int K, int lda, int ldb, int ldc,
    long long aSb, long long aSh, long long bSb, long long bSh,
    long long cSb, long long cSh,
    int mode, const int* __restrict__ mask, const float* __restrict__ rsPtr)
{
    constexpr int BM = 128, BN = 128;
    constexpr int ATILE = BM * 64;     // bytes (half): 128 rows x 32 halfs
    constexpr int STAGE = (BM + BN) * 64;  // 16384

    extern __shared__ char dsm_raw[];
    const uint32_t dyn0 = smem_u32(dsm_raw);
    const uint32_t sbase = (dyn0 + 1023u) & ~1023u;
    char* sm = dsm_raw + (sbase - dyn0);

    const int tid  = threadIdx.x;
    const int warp = tid >> 5, lane = tid & 31;
    const int wm   = warp >> 1, wn = warp & 1;
    const int g    = lane >> 2, tg = lane & 3;
    const int seg  = lane >> 3;

    const int z = blockIdx.z, bb = z >> 4, hh = z & 15;
    const __half* Ah = (const __half*)Av + (AH ? (size_t)(bb * aSb + hh * aSh) : 0);
    const float*  Af = (const float*) Av + (AH ? 0 : (size_t)(bb * aSb + hh * aSh));
    const __half* Bh = (const __half*)Bv + (BH ? (size_t)(bb * bSb + hh * bSh) : 0);
    const float*  Bf = (const float*) Bv + (BH ? 0 : (size_t)(bb * bSb + hh * bSh));
    __half* Coh = (__half*)Cv + (OH ? (size_t)(bb * cSb + hh * cSh) : 0);
    float*  Cof = (float*) Cv + (OH ? 0 : (size_t)(bb * cSb + hh * cSh));

    const int rowA0 = blockIdx.y * BM;
    const int rowB0 = blockIdx.x * BN;

    // ldmatrix per-lane base offsets (pre-swizzle, bytes within tile)
    const int frow = (seg & 1) * 8 + (lane & 7);
    const uint32_t aLane = (uint32_t)((wm * 32 + frow) * 64 + (seg >> 1) * 16);
    const uint32_t bLane = (uint32_t)((wn * 64 + frow) * 64 + (seg >> 1) * 16);

    // staging geometry: 2 chunks (16B of halfs) per thread per tile side
    int srow[2], skc[2];
#pragma unroll
    for (int r = 0; r < 2; r++) {
        int ch = tid + r * 256;
        srow[r] = ch >> 2;
        skc[r]  = ch & 3;
    }

    float acc[2][8][4];
#pragma unroll
    for (int mi = 0; mi < 2; mi++)
#pragma unroll
        for (int ni = 0; ni < 8; ni++)
#pragma unroll
            for (int q = 0; q < 4; q++) acc[mi][ni][q] = 0.f;

    const int nkt = K >> 5;
    uint4 pa[2], pb[2];

    // ---- load k-tile, returning packed half uint4 per chunk ----
    auto loadA = [&](int kt) {
#pragma unroll
        for (int r = 0; r < 2; r++) {
            const size_t off = (size_t)(rowA0 + srow[r]) * lda + kt * 32 + skc[r] * 8;
            if (AH) {
                pa[r] = *(const uint4*)(Ah + off);
            } else {
                float4 f0 = *(const float4*)(Af + off);
                float4 f1 = *(const float4*)(Af + off + 4);
                pa[r].x = pack2(f0.x, f0.y); pa[r].y = pack2(f0.z, f0.w);
                pa[r].z = pack2(f1.x, f1.y); pa[r].w = pack2(f1.z, f1.w);
            }
        }
#pragma unroll
        for (int r = 0; r < 2; r++) {
            const size_t off = (size_t)(rowB0 + srow[r]) * ldb + kt * 32 + skc[r] * 8;
            if (BH) {
                pb[r] = *(const uint4*)(Bh + off);
            } else {
                float4 f0 = *(const float4*)(Bf + off);
                float4 f1 = *(const float4*)(Bf + off + 4);
                pb[r].x = pack2(f0.x, f0.y); pb[r].y = pack2(f0.z, f0.w);
                pb[r].z = pack2(f1.x, f1.y); pb[r].w = pack2(f1.z, f1.w);
            }
        }
    };
    auto storeStage = [&](int buf) {
        char* sb = sm + buf * STAGE;
#pragma unroll
        for (int r = 0; r < 2; r++) {
            uint32_t o = SWZ((uint32_t)(srow[r] * 64 + skc[r] * 16));
            *(uint4*)(sb + o) = pa[r];
        }
#pragma unroll
        for (int r = 0; r < 2; r++) {
            uint32_t o = SWZ((uint32_t)(srow[r] * 64 + skc[r] * 16));
            *(uint4*)(sb + ATILE + o) = pb[r];
        }
    };

    // prologue
    loadA(0);
    storeStage(0);
    __syncthreads();

    int cur = 0;
    for (int kt = 0; kt < nkt; kt++) {
        if (kt + 1 < nkt) loadA(kt + 1);

        const uint32_t sa = sbase + cur * STAGE;
        const uint32_t sb = sa + ATILE;
#pragma unroll
        for (int ks = 0; ks < 2; ks++) {
            unsigned af[2][4];
#pragma unroll
            for (int mi = 0; mi < 2; mi++) {
                uint32_t o = SWZ(aLane + (uint32_t)(mi * 1024 + ks * 32));
                ldsm4(af[mi][0], af[mi][1], af[mi][2], af[mi][3], sa + o);
            }
            unsigned bf[8][2];
#pragma unroll
            for (int np = 0; np < 4; np++) {
                unsigned r0, r1, r2, r3;
                uint32_t o = SWZ(bLane + (uint32_t)(np * 1024 + ks * 32));
                ldsm4(r0, r1, r2, r3, sb + o);
                bf[np * 2 + 0][0] = r0; bf[np * 2 + 0][1] = r2;
                bf[np * 2 + 1][0] = r1; bf[np * 2 + 1][1] = r3;
            }
#pragma unroll
            for (int mi = 0; mi < 2; mi++)
#pragma unroll
                for (int ni = 0; ni < 8; ni++)
                    mma16816(acc[mi][ni], af[mi], bf[ni]);
        }

        if (kt + 1 < nkt) {
            storeStage(cur ^ 1);
            __syncthreads();
        }
        cur ^= 1;
    }

    // ---- epilogue ----
    float rs = 1.0f;
    if (mode == 2) rs = fminf(fmaxf(*rsPtr, 0.f), 0.3f);
    const float INV_SC = 0.08838834764831845f;  // 1/sqrt(128)

#pragma unroll
    for (int mi = 0; mi < 2; mi++) {
#pragma unroll
        for (int half_ = 0; half_ < 2; half_++) {
            const int row = rowA0 + wm * 32 + mi * 16 + g + half_ * 8;
#pragma unroll
            for (int ni = 0; ni < 8; ni++) {
                const int col = rowB0 + wn * 64 + ni * 8 + 2 * tg;
                float v0 = acc[mi][ni][half_ * 2 + 0];
                float v1 = acc[mi][ni][half_ * 2 + 1];
                if (mode == 1) {
                    v0 *= INV_SC; v1 *= INV_SC;
                    v0 = fminf(fmaxf(v0, -50.f), 50.f);
                    v1 = fminf(fmaxf(v1, -50.f), 50.f);
                    if (mask[bb * CT + col]     == 0) v0 = -50.f;
                    if (mask[bb * CT + col + 1] == 0) v1 = -50.f;
                } else {
                    if (bias) { v0 += bias[col]; v1 += bias[col + 1]; }
                    if (mode == 2) { v0 *= rs; v1 *= rs; }
                }
                if (OH) {
                    *(__half2*)(Coh + (size_t)row * ldc + col) = __floats2half2_rn(v0, v1);
                } else {
                    *(float2*)(Cof + (size_t)row * ldc + col) = make_float2(v0, v1);
                }
            }
        }
    }
}

// ---------------- V transpose: (b,t,h0,d) -> (b,h0,d,t), half ----------------
__global__ void transpose_v(const __half* __restrict__ V, __half* __restrict__ Vt) {
    __shared__ __half tile[32][33];
    const int z  = blockIdx.z;
    const int bb = z >> 4, hh = z & 15;
    const __half* src = V + (size_t)bb * CT * CH + hh * CHD;
    __half*       dst = Vt + (size_t)z * CHD * CT;
    const int t0 = blockIdx.x * 32, d0 = blockIdx.y * 32;
#pragma unroll
    for (int i = 0; i < 4; i++) {
        int t = t0 + threadIdx.y + i * 8;
        tile[threadIdx.y + i * 8][threadIdx.x] = src[(size_t)t * CH + d0 + threadIdx.x];
    }
    __syncthreads();
#pragma unroll
    for (int i = 0; i < 4; i++) {
        int d = d0 + threadIdx.y + i * 8;
        dst[(size_t)d * CT + t0 + threadIdx.x] = tile[threadIdx.x][threadIdx.y + i * 8];
    }
}

// ---------------- softmax over rows of 256: f32 in, half out ----------------
__global__ void softmax_kernel(const float* __restrict__ Sc, __half* __restrict__ P) {
    const int warp = threadIdx.x >> 5, lane = threadIdx.x & 31;
    const size_t row = (size_t)blockIdx.x * 8 + warp;
    const float4* p = (const float4*)(Sc + row * CT);
    float4 a = p[lane];
    float4 b = p[lane + 32];
    float m = fmaxf(fmaxf(fmaxf(a.x, a.y), fmaxf(a.z, a.w)),
                    fmaxf(fmaxf(b.x, b.y), fmaxf(b.z, b.w)));
#pragma unroll
    for (int o = 16; o; o >>= 1) m = fmaxf(m, __shfl_xor_sync(0xffffffffu, m, o));
    a.x = __expf(a.x - m); a.y = __expf(a.y - m); a.z = __expf(a.z - m); a.w = __expf(a.w - m);
    b.x = __expf(b.x - m); b.y = __expf(b.y - m); b.z = __expf(b.z - m); b.w = __expf(b.w - m);
    float s = a.x + a.y + a.z + a.w + b.x + b.y + b.z + b.w;
#pragma unroll
    for (int o = 16; o; o >>= 1) s += __shfl_xor_sync(0xffffffffu, s, o);
    const float inv = 1.f / s;
    __half2* q = (__half2*)(P + row * CT);
    q[lane * 2 + 0]  = __floats2half2_rn(a.x * inv, a.y * inv);
    q[lane * 2 + 1]  = __floats2half2_rn(a.z * inv, a.w * inv);
    q[64 + lane * 2] = __floats2half2_rn(b.x * inv, b.y * inv);
    q[65 + lane * 2] = __floats2half2_rn(b.z * inv, b.w * inv);
}

// ---------------- LayerNorm in place over rows of 2048 ----------------
__global__ void ln_kernel(float* __restrict__ X,
                          const float* __restrict__ gamma,
                          const float* __restrict__ beta) {
    __shared__ float red[8];
    __shared__ float sstat[2];
    const int tid = threadIdx.x, lane = tid & 31, warp = tid >> 5;
    float* p = X + (size_t)blockIdx.x * CH;
    float4 v0 = ((const float4*)p)[tid];
    float4 v1 = ((const float4*)p)[tid + 256];

    float s = v0.x + v0.y + v0.z + v0.w + v1.x + v1.y + v1.z + v1.w;
#pragma unroll
    for (int o = 16; o; o >>= 1) s += __shfl_xor_sync(0xffffffffu, s, o);
    if (lane == 0) red[warp] = s;
    __syncthreads();
    if (tid == 0) {
        float t = 0.f;
#pragma unroll
        for (int i = 0; i < 8; i++) t += red[i];
        sstat[0] = t * (1.f / CH);
    }
    __syncthreads();
    const float mu = sstat[0];

    float q = 0.f;
    {
        float d;
        d = v0.x - mu; q += d * d; d = v0.y - mu; q += d * d;
        d = v0.z - mu; q += d * d; d = v0.w - mu; q += d * d;
        d = v1.x - mu; q += d * d; d = v1.y - mu; q += d * d;
        d = v1.z - mu; q += d * d; d = v1.w - mu; q += d * d;
    }
#pragma unroll
    for (int o = 16; o; o >>= 1) q += __shfl_xor_sync(0xffffffffu, q, o);
    __syncthreads();
    if (lane == 0) red[warp] = q;
    __syncthreads();
    if (tid == 0) {
        float t = 0.f;
#pragma unroll
        for (int i = 0; i < 8; i++) t += red[i];
        sstat[1] = rsqrtf(t * (1.f / CH) + 1e-5f);
    }
    __syncthreads();
    const float inv = sstat[1];

    float4 gm0 = ((const float4*)gamma)[tid];
    float4 gm1 = ((const float4*)gamma)[tid + 256];
    float4 bt0 = ((const float4*)beta)[tid];
    float4 bt1 = ((const float4*)beta)[tid + 256];
    v0.x = (v0.x - mu) * inv * gm0.x + bt0.x;
    v0.y = (v0.y - mu) * inv * gm0.y + bt0.y;
    v0.z = (v0.z - mu) * inv * gm0.z + bt0.z;
    v0.w = (v0.w - mu) * inv * gm0.w + bt0.w;
    v1.x = (v1.x - mu) * inv * gm1.x + bt1.x;
    v1.y = (v1.y - mu) * inv * gm1.y + bt1.y;
    v1.z = (v1.z - mu) * inv * gm1.z + bt1.z;
    v1.w = (v1.w - mu) * inv * gm1.w + bt1.w;
    ((float4*)p)[tid] = v0;
    ((float4*)p)[tid + 256] = v1;
}

// ---------------- host launch ----------------
extern "C" void kernel_launch(void* const* d_in, const int* in_sizes, int n_in,
                              void* d_out, int out_size) {
    const float* hs  = (const float*)d_in[0];
    const float* at  = (const float*)d_in[1];
    const int*   msk = (const int*)  d_in[2];
    const float* Wq  = (const float*)d_in[3];
    const float* bq  = (const float*)d_in[4];
    const float* Wk  = (const float*)d_in[5];
    const float* bk  = (const float*)d_in[6];
    const float* Wv  = (const float*)d_in[7];
    const float* bv  = (const float*)d_in[8];
    const float* Wo  = (const float*)d_in[9];
    const float* bo  = (const float*)d_in[10];
    const float* gm  = (const float*)d_in[11];
    const float* bt  = (const float*)d_in[12];
    const float* rs  = (const float*)d_in[13];
    float* out = (float*)d_out;

    __half *Qh, *Kh, *Vh, *Vth, *Ph, *Cxh;
    float *Sc;
    cudaGetSymbolAddress((void**)&Qh,  g_Qh);
    cudaGetSymbolAddress((void**)&Kh,  g_Kh);
    cudaGetSymbolAddress((void**)&Vh,  g_Vh);
    cudaGetSymbolAddress((void**)&Vth, g_Vth);
    cudaGetSymbolAddress((void**)&Sc,  g_Sc);
    cudaGetSymbolAddress((void**)&Ph,  g_Ph);
    cudaGetSymbolAddress((void**)&Cxh, g_Cxh);

    const int SMEM = 2 * (128 + 128) * 64 + 1024;  // 33792 < 48KB

    // Q projection: (B*S, H) = hs * Wq^T + bq -> half
    hgemm<false, false, true><<<dim3(CH / 128, (CB * CS) / 128, 1), 256, SMEM>>>(
        hs, Wq, bq, Qh, CH, CH, CH, CH,
        0, 0, 0, 0, 0, 0, 0, nullptr, nullptr);

    // K projection -> half
    hgemm<false, false, true><<<dim3(CH / 128, (CB * CT) / 128, 1), 256, SMEM>>>(
        at, Wk, bk, Kh, CH, CH, CH, CH,
        0, 0, 0, 0, 0, 0, 0, nullptr, nullptr);

    // V projection -> half
    hgemm<false, false, true><<<dim3(CH / 128, (CB * CT) / 128, 1), 256, SMEM>>>(
        at, Wv, bv, Vh, CH, CH, CH, CH,
        0, 0, 0, 0, 0, 0, 0, nullptr, nullptr);

    // V transpose per head (half)
    transpose_v<<<dim3(CT / 32, CHD / 32, CB * CNH), dim3(32, 8)>>>(Vh, Vth);

    // scores: per (b,h) S[s,t] = Q_bh * K_bh^T -> f32, scaled/clipped/masked
    hgemm<true, true, false><<<dim3(CT / 128, CS / 128, CB * CNH), 256, SMEM>>>(
        Qh, Kh, nullptr, Sc, CHD, CH, CH, CT,
        (long long)CS * CH, (long long)CHD,
        (long long)CT * CH, (long long)CHD,
        (long long)CNH * CS * CT, (long long)CS * CT,
        1, msk, nullptr);

    // softmax rows: f32 -> half probs
    softmax_kernel<<<(CB * CNH * CS) / 8, 256>>>(Sc, Ph);

    // ctx: per (b,h) C[s,d] = P * V -> half, (b,s,h) layout
    hgemm<true, true, true><<<dim3(CHD / 128, CS / 128, CB * CNH), 256, SMEM>>>(
        Ph, Vth, nullptr, Cxh, CT, CT, CT, CH,
        (long long)CNH * CS * CT, (long long)CS * CT,
        (long long)CNH * CHD * CT, (long long)CHD * CT,
        (long long)CS * CH, (long long)CHD,
        0, nullptr, nullptr);

    // O projection with bias + residual scale -> f32 out
    hgemm<true, false, false><<<dim3(CH / 128, (CB * CS) / 128, 1), 256, SMEM>>>(
        Cxh, Wo, bo, out, CH, CH, CH, CH,
        0, 0, 0, 0, 0, 0, 2, nullptr, rs);

    // LayerNorm in place
    ln_kernel<<<CB * CS, 256>>>(out, gm, bt);
}